// round 2
// baseline (speedup 1.0000x reference)
#include <cuda_runtime.h>
#include <math.h>

#define NB    8192
#define D_IN  256
#define NH1   512
#define NH2   256
#define D_OUT 64

// Scratch (allocation-free rule: __device__ globals)
__device__ float g_h1[NB * NH1];
__device__ float g_h2[NB * NH2];
__device__ float g_out[NB * D_OUT];
__device__ float g_normed[NB * D_OUT];

// ---------------------------------------------------------------------------
// Generic NT GEMM: C[M,N] = act(A[M,K] @ B[N,K]^T + bias[N])
// Tiles: BM=BN=64, BK=32; 256 threads; 4x4 microtile per thread.
// ---------------------------------------------------------------------------
template <int ACT>
__global__ void gemm_nt(const float* __restrict__ A, const float* __restrict__ Bm,
                        const float* __restrict__ bias, float* __restrict__ C,
                        int M, int N, int K) {
    __shared__ float sA[64][33];
    __shared__ float sB[64][33];

    const int tid = threadIdx.x;
    const int tx = tid & 15;
    const int ty = tid >> 4;
    const int m0 = blockIdx.x * 64;
    const int n0 = blockIdx.y * 64;

    float acc[4][4];
#pragma unroll
    for (int i = 0; i < 4; i++)
#pragma unroll
        for (int j = 0; j < 4; j++) acc[i][j] = 0.0f;

    const int lrow = tid >> 3;        // 0..31
    const int lcol = (tid & 7) * 4;   // 0,4,...,28

    for (int k0 = 0; k0 < K; k0 += 32) {
        // Load A tile 64x32 (two row-halves), float4 coalesced
        {
            float4 a0 = *(const float4*)&A[(size_t)(m0 + lrow) * K + k0 + lcol];
            float4 a1 = *(const float4*)&A[(size_t)(m0 + lrow + 32) * K + k0 + lcol];
            sA[lrow][lcol + 0] = a0.x; sA[lrow][lcol + 1] = a0.y;
            sA[lrow][lcol + 2] = a0.z; sA[lrow][lcol + 3] = a0.w;
            sA[lrow + 32][lcol + 0] = a1.x; sA[lrow + 32][lcol + 1] = a1.y;
            sA[lrow + 32][lcol + 2] = a1.z; sA[lrow + 32][lcol + 3] = a1.w;

            float4 b0 = *(const float4*)&Bm[(size_t)(n0 + lrow) * K + k0 + lcol];
            float4 b1 = *(const float4*)&Bm[(size_t)(n0 + lrow + 32) * K + k0 + lcol];
            sB[lrow][lcol + 0] = b0.x; sB[lrow][lcol + 1] = b0.y;
            sB[lrow][lcol + 2] = b0.z; sB[lrow][lcol + 3] = b0.w;
            sB[lrow + 32][lcol + 0] = b1.x; sB[lrow + 32][lcol + 1] = b1.y;
            sB[lrow + 32][lcol + 2] = b1.z; sB[lrow + 32][lcol + 3] = b1.w;
        }
        __syncthreads();

#pragma unroll 8
        for (int k = 0; k < 32; k++) {
            float a[4], b[4];
#pragma unroll
            for (int ii = 0; ii < 4; ii++) a[ii] = sA[ty * 4 + ii][k];
#pragma unroll
            for (int jj = 0; jj < 4; jj++) b[jj] = sB[tx * 4 + jj][k];
#pragma unroll
            for (int ii = 0; ii < 4; ii++)
#pragma unroll
                for (int jj = 0; jj < 4; jj++)
                    acc[ii][jj] = fmaf(a[ii], b[jj], acc[ii][jj]);
        }
        __syncthreads();
    }

#pragma unroll
    for (int ii = 0; ii < 4; ii++) {
        int m = m0 + ty * 4 + ii;
#pragma unroll
        for (int jj = 0; jj < 4; jj++) {
            int n = n0 + tx * 4 + jj;
            float v = acc[ii][jj] + bias[n];
            if (ACT) v = tanhf(v);
            C[(size_t)m * N + n] = v;
        }
    }
}

// ---------------------------------------------------------------------------
// Row normalization: normed = out / (||out|| + 1e-12), rows of length 64
// ---------------------------------------------------------------------------
__global__ void normalize_kernel(const float* __restrict__ outv,
                                 float* __restrict__ normed) {
    int row = blockIdx.x;
    int lane = threadIdx.x;  // 0..63 (2 warps)
    __shared__ float partial[2];

    float v = outv[row * 64 + lane];
    float s = v * v;
#pragma unroll
    for (int o = 16; o > 0; o >>= 1) s += __shfl_xor_sync(0xffffffffu, s, o);
    if ((lane & 31) == 0) partial[lane >> 5] = s;
    __syncthreads();
    float tot = partial[0] + partial[1];
    float inv = 1.0f / (sqrtf(tot) + 1e-12f);
    normed[row * 64 + lane] = v * inv;
}

// ---------------------------------------------------------------------------
// Fused pair kernel: for each 64-row i-block, sweep all j-tiles:
//   S = Ni @ Nj^T (fp32), mask = (S*S >= 0.9 && i != j), acc += mask @ out_j
// Adjacency matrix never materialized in global memory.
// smem layout (dynamic): sNi [64][65], sNj [64][65] (reused as mask), sOj [64][68]
// ---------------------------------------------------------------------------
#define SNI(r, c) sNi[(r) * 65 + (c)]
#define SNJ(r, c) sNj[(r) * 65 + (c)]
#define SOJ(r, c) sOj[(r) * 68 + (c)]

__global__ void pair_kernel(const float* __restrict__ normed,
                            const float* __restrict__ outv,
                            float* __restrict__ res) {
    extern __shared__ float smem[];
    float* sNi = smem;                 // 64*65 = 4160 floats
    float* sNj = smem + 64 * 65;       // 64*65  (reused as mask buffer)
    float* sOj = smem + 2 * 64 * 65;   // 64*68 = 4352 floats (16B-aligned rows)

    const int tid = threadIdx.x;
    const int tx = tid & 15;
    const int ty = tid >> 4;
    const int i0 = blockIdx.x * 64;

    // Load Ni tile once (64x64), float4 from gmem, scalar into padded smem
    for (int idx = tid; idx < 64 * 16; idx += 256) {
        int r = idx >> 4, c4 = (idx & 15) * 4;
        float4 v = *(const float4*)&normed[(size_t)(i0 + r) * 64 + c4];
        SNI(r, c4 + 0) = v.x; SNI(r, c4 + 1) = v.y;
        SNI(r, c4 + 2) = v.z; SNI(r, c4 + 3) = v.w;
    }

    float acc[4][4];
#pragma unroll
    for (int i = 0; i < 4; i++)
#pragma unroll
        for (int j = 0; j < 4; j++) acc[i][j] = 0.0f;

    for (int j0 = 0; j0 < NB; j0 += 64) {
        __syncthreads();  // protect sNj/sOj from previous iteration's readers
        for (int idx = tid; idx < 64 * 16; idx += 256) {
            int r = idx >> 4, c4 = (idx & 15) * 4;
            float4 v = *(const float4*)&normed[(size_t)(j0 + r) * 64 + c4];
            SNJ(r, c4 + 0) = v.x; SNJ(r, c4 + 1) = v.y;
            SNJ(r, c4 + 2) = v.z; SNJ(r, c4 + 3) = v.w;
            float4 w = *(const float4*)&outv[(size_t)(j0 + r) * 64 + c4];
            *(float4*)&SOJ(r, c4) = w;
        }
        __syncthreads();

        // S = Ni @ Nj^T over d = 0..63 (4x4 per thread)
        float S[4][4];
#pragma unroll
        for (int i = 0; i < 4; i++)
#pragma unroll
            for (int j = 0; j < 4; j++) S[i][j] = 0.0f;

#pragma unroll 16
        for (int d = 0; d < 64; d++) {
            float a[4], b[4];
#pragma unroll
            for (int ii = 0; ii < 4; ii++) a[ii] = SNI(ty * 4 + ii, d);
#pragma unroll
            for (int jj = 0; jj < 4; jj++) b[jj] = SNJ(tx * 4 + jj, d);
#pragma unroll
            for (int ii = 0; ii < 4; ii++)
#pragma unroll
                for (int jj = 0; jj < 4; jj++)
                    S[ii][jj] = fmaf(a[ii], b[jj], S[ii][jj]);
        }
        __syncthreads();

        // Threshold -> mask written into sNj storage
#pragma unroll
        for (int ii = 0; ii < 4; ii++) {
            int gi = i0 + ty * 4 + ii;
#pragma unroll
            for (int jj = 0; jj < 4; jj++) {
                int gj = j0 + tx * 4 + jj;
                float dot = S[ii][jj];
                float m = (dot * dot >= 0.9f && gi != gj) ? 1.0f : 0.0f;
                SNJ(ty * 4 + ii, tx * 4 + jj) = m;
            }
        }
        __syncthreads();

        // acc += mask @ out_j
#pragma unroll 8
        for (int tj = 0; tj < 64; tj++) {
            float a[4];
#pragma unroll
            for (int ii = 0; ii < 4; ii++) a[ii] = SNJ(ty * 4 + ii, tj);
            float4 bv = *(const float4*)&SOJ(tj, tx * 4);
#pragma unroll
            for (int ii = 0; ii < 4; ii++) {
                acc[ii][0] = fmaf(a[ii], bv.x, acc[ii][0]);
                acc[ii][1] = fmaf(a[ii], bv.y, acc[ii][1]);
                acc[ii][2] = fmaf(a[ii], bv.z, acc[ii][2]);
                acc[ii][3] = fmaf(a[ii], bv.w, acc[ii][3]);
            }
        }
    }

    // Store result (covers every element; no pre-zero needed)
#pragma unroll
    for (int ii = 0; ii < 4; ii++) {
        float4 v = make_float4(acc[ii][0], acc[ii][1], acc[ii][2], acc[ii][3]);
        *(float4*)&res[(size_t)(i0 + ty * 4 + ii) * 64 + tx * 4] = v;
    }
}

// ---------------------------------------------------------------------------
extern "C" void kernel_launch(void* const* d_in, const int* in_sizes, int n_in,
                              void* d_out, int out_size) {
    const float* x  = (const float*)d_in[0];
    const float* W1 = (const float*)d_in[1];
    const float* b1 = (const float*)d_in[2];
    const float* W2 = (const float*)d_in[3];
    const float* b2 = (const float*)d_in[4];
    const float* W3 = (const float*)d_in[5];
    const float* b3 = (const float*)d_in[6];
    float* res = (float*)d_out;

    float *h1, *h2, *outv, *normed;
    cudaGetSymbolAddress((void**)&h1, g_h1);
    cudaGetSymbolAddress((void**)&h2, g_h2);
    cudaGetSymbolAddress((void**)&outv, g_out);
    cudaGetSymbolAddress((void**)&normed, g_normed);

    // MLP
    gemm_nt<1><<<dim3(NB / 64, NH1 / 64), 256>>>(x,  W1, b1, h1,  NB, NH1, D_IN);
    gemm_nt<1><<<dim3(NB / 64, NH2 / 64), 256>>>(h1, W2, b2, h2,  NB, NH2, NH1);
    gemm_nt<0><<<dim3(NB / 64, D_OUT / 64), 256>>>(h2, W3, b3, outv, NB, D_OUT, NH2);

    // Normalize rows
    normalize_kernel<<<NB, 64>>>(outv, normed);

    // Fused fidelity-threshold-aggregate
    size_t smem_bytes = (size_t)(2 * 64 * 65 + 64 * 68) * sizeof(float);  // 50688 B
    cudaFuncSetAttribute(pair_kernel, cudaFuncAttributeMaxDynamicSharedMemorySize,
                         (int)smem_bytes);
    pair_kernel<<<NB / 64, 256, smem_bytes>>>(normed, outv, res);
}

// round 6
// speedup vs baseline: 1.0773x; 1.0773x over previous
#include <cuda_runtime.h>
#include <math.h>

#define NB    8192
#define D_IN  256
#define NH1   512
#define NH2   256
#define D_OUT 64

// Scratch (allocation-free rule: __device__ globals)
__device__ float g_h1[NB * NH1];
__device__ float g_h2[NB * NH2];
__device__ float g_out[NB * D_OUT];
__device__ float g_normed[NB * D_OUT];

typedef unsigned long long u64;

// Packed fp32x2 FMA (Blackwell FFMA2). Elementwise .rn — bit-identical to fmaf.
__device__ __forceinline__ void ffma2(u64& d, u64 a, u64 b) {
    asm("fma.rn.f32x2 %0, %1, %2, %3;" : "=l"(d) : "l"(a), "l"(b), "l"(d));
}
__device__ __forceinline__ u64 splat2(float x) {
    u64 r; unsigned xi = __float_as_uint(x);
    asm("mov.b64 %0, {%1, %1};" : "=l"(r) : "r"(xi));
    return r;
}
__device__ __forceinline__ float lo32(u64 v) { return __uint_as_float((unsigned)v); }
__device__ __forceinline__ float hi32(u64 v) { return __uint_as_float((unsigned)(v >> 32)); }

// ---------------------------------------------------------------------------
// NT GEMM: C[M,N] = act(A[M,K] @ B[N,K]^T + bias[N])
// BM=BN=64, BK=32; 256 threads; 4x4 microtile; k-major transposed smem tiles
// so the inner loop is 2x LDS.128 + 4 splats + 8 FFMA2 per k.
// ---------------------------------------------------------------------------
template <int ACT>
__global__ void gemm_nt(const float* __restrict__ A, const float* __restrict__ Bm,
                        const float* __restrict__ bias, float* __restrict__ C,
                        int M, int N, int K) {
    __shared__ float sAT[32][68];   // [k][m], rows 16B-aligned (68*4=272)
    __shared__ float sBT[32][68];   // [k][n]

    const int tid = threadIdx.x;
    const int tx = tid & 15;
    const int ty = tid >> 4;
    const int m0 = blockIdx.x * 64;
    const int n0 = blockIdx.y * 64;

    u64 acc2[4][2];   // [jj][p]; p=0 -> ii{0,1}, p=1 -> ii{2,3}
#pragma unroll
    for (int j = 0; j < 4; j++) { acc2[j][0] = 0ull; acc2[j][1] = 0ull; }

    const int lrow = tid >> 3;        // 0..31
    const int lcol = (tid & 7) * 4;   // 0,4,...,28

    for (int k0 = 0; k0 < K; k0 += 32) {
        {
            float4 a0 = *(const float4*)&A[(size_t)(m0 + lrow) * K + k0 + lcol];
            float4 a1 = *(const float4*)&A[(size_t)(m0 + lrow + 32) * K + k0 + lcol];
            sAT[lcol + 0][lrow] = a0.x; sAT[lcol + 1][lrow] = a0.y;
            sAT[lcol + 2][lrow] = a0.z; sAT[lcol + 3][lrow] = a0.w;
            sAT[lcol + 0][lrow + 32] = a1.x; sAT[lcol + 1][lrow + 32] = a1.y;
            sAT[lcol + 2][lrow + 32] = a1.z; sAT[lcol + 3][lrow + 32] = a1.w;

            float4 b0 = *(const float4*)&Bm[(size_t)(n0 + lrow) * K + k0 + lcol];
            float4 b1 = *(const float4*)&Bm[(size_t)(n0 + lrow + 32) * K + k0 + lcol];
            sBT[lcol + 0][lrow] = b0.x; sBT[lcol + 1][lrow] = b0.y;
            sBT[lcol + 2][lrow] = b0.z; sBT[lcol + 3][lrow] = b0.w;
            sBT[lcol + 0][lrow + 32] = b1.x; sBT[lcol + 1][lrow + 32] = b1.y;
            sBT[lcol + 2][lrow + 32] = b1.z; sBT[lcol + 3][lrow + 32] = b1.w;
        }
        __syncthreads();

#pragma unroll 8
        for (int k = 0; k < 32; k++) {
            ulonglong2 ap = *(const ulonglong2*)&sAT[k][ty * 4];
            float4 bv = *(const float4*)&sBT[k][tx * 4];
            u64 bs0 = splat2(bv.x), bs1 = splat2(bv.y);
            u64 bs2 = splat2(bv.z), bs3 = splat2(bv.w);
            ffma2(acc2[0][0], ap.x, bs0); ffma2(acc2[0][1], ap.y, bs0);
            ffma2(acc2[1][0], ap.x, bs1); ffma2(acc2[1][1], ap.y, bs1);
            ffma2(acc2[2][0], ap.x, bs2); ffma2(acc2[2][1], ap.y, bs2);
            ffma2(acc2[3][0], ap.x, bs3); ffma2(acc2[3][1], ap.y, bs3);
        }
        __syncthreads();
    }

#pragma unroll
    for (int ii = 0; ii < 4; ii++) {
        int m = m0 + ty * 4 + ii;
        float v[4];
#pragma unroll
        for (int jj = 0; jj < 4; jj++) {
            u64 a = acc2[jj][ii >> 1];
            float s = (ii & 1) ? hi32(a) : lo32(a);
            s += bias[n0 + tx * 4 + jj];
            if (ACT) s = tanhf(s);
            v[jj] = s;
        }
        *(float4*)&C[(size_t)m * N + n0 + tx * 4] = make_float4(v[0], v[1], v[2], v[3]);
    }
}

// ---------------------------------------------------------------------------
// Row normalization: normed = out / (||out|| + 1e-12), rows of length 64
// ---------------------------------------------------------------------------
__global__ void normalize_kernel(const float* __restrict__ outv,
                                 float* __restrict__ normed) {
    int row = blockIdx.x;
    int lane = threadIdx.x;  // 0..63
    __shared__ float partial[2];

    float v = outv[row * 64 + lane];
    float s = v * v;
#pragma unroll
    for (int o = 16; o > 0; o >>= 1) s += __shfl_xor_sync(0xffffffffu, s, o);
    if ((lane & 31) == 0) partial[lane >> 5] = s;
    __syncthreads();
    float tot = partial[0] + partial[1];
    float inv = 1.0f / (sqrtf(tot) + 1e-12f);
    normed[row * 64 + lane] = v * inv;
}

// ---------------------------------------------------------------------------
// Fused pair kernel (FFMA2): per 64x64 (i,j) tile:
//   S = Ni @ Nj^T (fp32), mask = (S*S >= 0.9 && i != j), acc += mask @ out_j
// Adjacency never materialized in gmem. All smem tiles d-major (transposed)
// so both inner loops are 2x LDS.128 + 4 splats + 8 FFMA2 per step.
// smem (dynamic): sNiT[64][68], sNjT[64][68] (reused as maskT), sOj[64][68]
// ---------------------------------------------------------------------------
#define PAD 68
__global__ void pair_kernel(const float* __restrict__ normed,
                            const float* __restrict__ outv,
                            float* __restrict__ res) {
    extern __shared__ float smem[];
    float* sNiT = smem;                  // [d][i]
    float* sNjT = smem + 64 * PAD;       // [d][j], reused as maskT[tj][i]
    float* sOj  = smem + 2 * 64 * PAD;   // [tj][n]

    const int tid = threadIdx.x;
    const int tx = tid & 15;
    const int ty = tid >> 4;
    const int i0 = blockIdx.x * 64;

    // Load Ni tile transposed: sNiT[c][r] = normed[i0+r][c]
    for (int idx = tid; idx < 64 * 16; idx += 256) {
        int r = idx >> 4, c4 = (idx & 15) * 4;
        float4 v = *(const float4*)&normed[(size_t)(i0 + r) * 64 + c4];
        sNiT[(c4 + 0) * PAD + r] = v.x; sNiT[(c4 + 1) * PAD + r] = v.y;
        sNiT[(c4 + 2) * PAD + r] = v.z; sNiT[(c4 + 3) * PAD + r] = v.w;
    }

    u64 acc2[4][2];   // result accumulator, [jj=out col][p over ii]
#pragma unroll
    for (int j = 0; j < 4; j++) { acc2[j][0] = 0ull; acc2[j][1] = 0ull; }

    for (int j0 = 0; j0 < NB; j0 += 64) {
        __syncthreads();  // protect sNjT/sOj from previous iteration's readers
        for (int idx = tid; idx < 64 * 16; idx += 256) {
            int r = idx >> 4, c4 = (idx & 15) * 4;
            float4 v = *(const float4*)&normed[(size_t)(j0 + r) * 64 + c4];
            sNjT[(c4 + 0) * PAD + r] = v.x; sNjT[(c4 + 1) * PAD + r] = v.y;
            sNjT[(c4 + 2) * PAD + r] = v.z; sNjT[(c4 + 3) * PAD + r] = v.w;
            float4 w = *(const float4*)&outv[(size_t)(j0 + r) * 64 + c4];
            *(float4*)&sOj[r * PAD + c4] = w;
        }
        __syncthreads();

        // S = Ni @ Nj^T over d = 0..63
        u64 S2[4][2];
#pragma unroll
        for (int j = 0; j < 4; j++) { S2[j][0] = 0ull; S2[j][1] = 0ull; }

#pragma unroll 8
        for (int d = 0; d < 64; d++) {
            ulonglong2 ap = *(const ulonglong2*)&sNiT[d * PAD + ty * 4];
            float4 bv = *(const float4*)&sNjT[d * PAD + tx * 4];
            u64 bs0 = splat2(bv.x), bs1 = splat2(bv.y);
            u64 bs2 = splat2(bv.z), bs3 = splat2(bv.w);
            ffma2(S2[0][0], ap.x, bs0); ffma2(S2[0][1], ap.y, bs0);
            ffma2(S2[1][0], ap.x, bs1); ffma2(S2[1][1], ap.y, bs1);
            ffma2(S2[2][0], ap.x, bs2); ffma2(S2[2][1], ap.y, bs2);
            ffma2(S2[3][0], ap.x, bs3); ffma2(S2[3][1], ap.y, bs3);
        }
        __syncthreads();  // done reading sNjT; about to overwrite with maskT

        // Threshold -> maskT[tj][i] stored in sNjT's storage
#pragma unroll
        for (int jj = 0; jj < 4; jj++) {
            int gj = j0 + tx * 4 + jj;
#pragma unroll
            for (int p = 0; p < 2; p++) {
                float d0 = lo32(S2[jj][p]);
                float d1 = hi32(S2[jj][p]);
                int gi0 = i0 + ty * 4 + 2 * p;
                float m0v = (d0 * d0 >= 0.9f && gi0 != gj) ? 1.0f : 0.0f;
                float m1v = (d1 * d1 >= 0.9f && (gi0 + 1) != gj) ? 1.0f : 0.0f;
                sNjT[gj % 64 * PAD + ty * 4 + 2 * p] = m0v;
                sNjT[gj % 64 * PAD + ty * 4 + 2 * p + 1] = m1v;
            }
        }
        __syncthreads();

        // acc += maskT^T @ out_j  (a = maskT[tj][i], b = sOj[tj][n])
#pragma unroll 8
        for (int tj = 0; tj < 64; tj++) {
            ulonglong2 ap = *(const ulonglong2*)&sNjT[tj * PAD + ty * 4];
            float4 bv = *(const float4*)&sOj[tj * PAD + tx * 4];
            u64 bs0 = splat2(bv.x), bs1 = splat2(bv.y);
            u64 bs2 = splat2(bv.z), bs3 = splat2(bv.w);
            ffma2(acc2[0][0], ap.x, bs0); ffma2(acc2[0][1], ap.y, bs0);
            ffma2(acc2[1][0], ap.x, bs1); ffma2(acc2[1][1], ap.y, bs1);
            ffma2(acc2[2][0], ap.x, bs2); ffma2(acc2[2][1], ap.y, bs2);
            ffma2(acc2[3][0], ap.x, bs3); ffma2(acc2[3][1], ap.y, bs3);
        }
    }

    // Store result (covers every element; no pre-zero needed)
#pragma unroll
    for (int ii = 0; ii < 4; ii++) {
        float v[4];
#pragma unroll
        for (int jj = 0; jj < 4; jj++) {
            u64 a = acc2[jj][ii >> 1];
            v[jj] = (ii & 1) ? hi32(a) : lo32(a);
        }
        *(float4*)&res[(size_t)(i0 + ty * 4 + ii) * 64 + tx * 4] =
            make_float4(v[0], v[1], v[2], v[3]);
    }
}

// ---------------------------------------------------------------------------
extern "C" void kernel_launch(void* const* d_in, const int* in_sizes, int n_in,
                              void* d_out, int out_size) {
    const float* x  = (const float*)d_in[0];
    const float* W1 = (const float*)d_in[1];
    const float* b1 = (const float*)d_in[2];
    const float* W2 = (const float*)d_in[3];
    const float* b2 = (const float*)d_in[4];
    const float* W3 = (const float*)d_in[5];
    const float* b3 = (const float*)d_in[6];
    float* res = (float*)d_out;

    float *h1, *h2, *outv, *normed;
    cudaGetSymbolAddress((void**)&h1, g_h1);
    cudaGetSymbolAddress((void**)&h2, g_h2);
    cudaGetSymbolAddress((void**)&outv, g_out);
    cudaGetSymbolAddress((void**)&normed, g_normed);

    // MLP
    gemm_nt<1><<<dim3(NB / 64, NH1 / 64), 256>>>(x,  W1, b1, h1,  NB, NH1, D_IN);
    gemm_nt<1><<<dim3(NB / 64, NH2 / 64), 256>>>(h1, W2, b2, h2,  NB, NH2, NH1);
    gemm_nt<0><<<dim3(NB / 64, D_OUT / 64), 256>>>(h2, W3, b3, outv, NB, D_OUT, NH2);

    // Normalize rows
    normalize_kernel<<<NB, 64>>>(outv, normed);

    // Fused fidelity-threshold-aggregate
    size_t smem_bytes = (size_t)(3 * 64 * PAD) * sizeof(float);  // 52224 B
    cudaFuncSetAttribute(pair_kernel, cudaFuncAttributeMaxDynamicSharedMemorySize,
                         (int)smem_bytes);
    pair_kernel<<<NB / 64, 256, smem_bytes>>>(normed, outv, res);
}